// round 11
// baseline (speedup 1.0000x reference)
#include <cuda_runtime.h>
#include <cuda_fp16.h>
#include <cstdint>
#include <cstddef>

#define BB 2
#define NN 10000
#define MM 320000
#define DD 256
#define HH 8

#define ROWS (BB*NN)   // 20000 rows per projection
#define BM 128
#define BNJ 64         // block n-tile
#define BK 16
#define NKT (DD/BK)    // 16 k-tiles

// Scratch (allocation-free rule: device globals)
__device__ __half g_qh[(size_t)BB*NN*DD];
__device__ __half g_kh[(size_t)BB*NN*DD];
__device__ float g_seg[(size_t)BB*NN*HH];
__device__ float g_inv[(size_t)BB*NN*HH];
__device__ int   g_is64;

// ---------------------------------------------------------------------------
// mask dtype detection: values in [0, N) so int64 high words are all zero.
// ---------------------------------------------------------------------------
__global__ void detect_kernel(const unsigned* __restrict__ w) {
    if (threadIdx.x == 0) {
        int is64 = 1;
        #pragma unroll 1
        for (int t = 0; t < 64; ++t) {
            if (w[2*t + 1] != 0u) { is64 = 0; break; }
        }
        g_is64 = is64;
    }
}

__device__ __forceinline__ int mask_at(const void* m, int row, int e, int is64) {
    if (is64) return (int)((const long long*)m)[(unsigned)(row*MM + e)];
    return ((const int*)m)[(unsigned)(row*MM + e)];
}

__global__ void zero_seg_kernel() {
    int i = blockIdx.x * blockDim.x + threadIdx.x;
    if (i < BB*NN*HH) g_seg[i] = 0.0f;
}

// ---------------------------------------------------------------------------
// FP16 tensor-core GEMM (m16n8k16, f32 accum).
// B (full K x 64n slice, fp16, 32KB) resident in smem: loaded ONCE in the
// prologue, so the steady-state per-tile barrier only waits on tiny A loads.
// A double-buffered with 1-tile register prefetch. XOR-swizzled smem
// (word = row*8 + (w ^ (row&7))): consumer banks are a permutation of 0..31.
// Y[20000,256](fp16) = X[20000,256] @ W[256,256];  z=0: q, z=1: k
// ---------------------------------------------------------------------------
__device__ __forceinline__ unsigned packh2(float a, float b) {
    __half2 h = __floats2half2_rn(a, b);   // lo=a, hi=b  (k, k+1)
    return *(unsigned*)&h;
}

__global__ __launch_bounds__(256, 2) void gemm_kernel(
    const float* __restrict__ x_q, const float* __restrict__ x_k,
    const float* __restrict__ w_q, const float* __restrict__ w_k)
{
    __shared__ unsigned As[2][BM * 8];          // 8 KB  (fp16, per-tile)
    __shared__ unsigned Bs[NKT][BNJ * 8];       // 32 KB (fp16, full K)

    const float* X = blockIdx.z ? x_k : x_q;
    const float* W = blockIdx.z ? w_k : w_q;
    __half*      Y = blockIdx.z ? g_kh : g_qh;

    const int m0   = blockIdx.x * BM;
    const int n0   = blockIdx.y * BNJ;
    const int tid  = threadIdx.x;
    const int lane = tid & 31;
    const int warp = tid >> 5;
    const int rB   = (warp & 3) * 32;   // warp row base (4 row-warps)
    const int nB   = (warp >> 2) * 32;  // warp col base (2 col-warps)

    // ---- B prologue: whole 256k x 64n slice -> smem, once ----
    #pragma unroll
    for (int it = 0; it < 8; ++it) {
        int idx = it * 256 + tid;      // 0..2047
        int p   = idx >> 4;            // k-pair 0..127  (k = 2p, 2p+1)
        int f4  = idx & 15;            // float4 index along n
        float4 r0 = *(const float4*)&W[(size_t)(2*p)   * DD + n0 + f4*4];
        float4 r1 = *(const float4*)&W[(size_t)(2*p+1) * DD + n0 + f4*4];
        unsigned* Bp = Bs[p >> 3];
        const int w  = p & 7;
        const int ln = f4 * 4;
        Bp[(ln+0)*8 + (w ^ ((ln+0)&7))] = packh2(r0.x, r1.x);
        Bp[(ln+1)*8 + (w ^ ((ln+1)&7))] = packh2(r0.y, r1.y);
        Bp[(ln+2)*8 + (w ^ ((ln+2)&7))] = packh2(r0.z, r1.z);
        Bp[(ln+3)*8 + (w ^ ((ln+3)&7))] = packh2(r0.w, r1.w);
    }

    // ---- A producer indices ----
    const int ar = tid >> 2;            // rows ar, ar+64
    const int wa = (tid & 3) * 2;       // word base (2 words = 4 floats)
    const int ac = (tid & 3) * 4;       // float col base
    const int sw = ar & 7;              // (ar+64)&7 == ar&7

    int gr0 = m0 + ar;      if (gr0 >= ROWS) gr0 = ROWS - 1;
    int gr1 = m0 + ar + 64; if (gr1 >= ROWS) gr1 = ROWS - 1;
    const float* xp0 = X + (size_t)gr0 * DD + ac;
    const float* xp1 = X + (size_t)gr1 * DD + ac;

    float c[2][4][4];
    #pragma unroll
    for (int mt = 0; mt < 2; ++mt)
        #pragma unroll
        for (int nt = 0; nt < 4; ++nt)
            #pragma unroll
            for (int r = 0; r < 4; ++r) c[mt][nt][r] = 0.0f;

    float4 a0v = *(const float4*)xp0;
    float4 a1v = *(const float4*)xp1;
    {   // store A tile 0 into buf 0
        unsigned* A = As[0];
        A[ar*8      + ((wa+0) ^ sw)] = packh2(a0v.x, a0v.y);
        A[ar*8      + ((wa+1) ^ sw)] = packh2(a0v.z, a0v.w);
        A[(ar+64)*8 + ((wa+0) ^ sw)] = packh2(a1v.x, a1v.y);
        A[(ar+64)*8 + ((wa+1) ^ sw)] = packh2(a1v.z, a1v.w);
    }
    __syncthreads();

    #pragma unroll 2
    for (int kt = 0; kt < NKT; ++kt) {
        // prefetch next A tile into registers (hidden behind compute)
        if (kt + 1 < NKT) {
            int ko = (kt + 1) * BK;
            a0v = *(const float4*)(xp0 + ko);
            a1v = *(const float4*)(xp1 + ko);
        }

        // compute: one m16n8k16 sweep covers BK=16
        {
            const unsigned* A  = As[kt & 1];
            const unsigned* Bp = Bs[kt];
            const int t = lane & 3;
            const int g = lane >> 2;
            unsigned a[2][4], b[4][2];
            #pragma unroll
            for (int mt = 0; mt < 2; ++mt) {
                int r = rB + mt * 16 + g;         // r&7 == g
                a[mt][0] = A[r*8     + (t ^ g)];
                a[mt][1] = A[(r+8)*8 + (t ^ g)];
                a[mt][2] = A[r*8     + ((t+4) ^ g)];
                a[mt][3] = A[(r+8)*8 + ((t+4) ^ g)];
            }
            #pragma unroll
            for (int nt = 0; nt < 4; ++nt) {
                int col = nB + nt * 8 + g;        // col&7 == g
                b[nt][0] = Bp[col*8 + (t ^ g)];
                b[nt][1] = Bp[col*8 + ((t+4) ^ g)];
            }
            #pragma unroll
            for (int mt = 0; mt < 2; ++mt)
                #pragma unroll
                for (int nt = 0; nt < 4; ++nt)
                    asm volatile(
                        "mma.sync.aligned.m16n8k16.row.col.f32.f16.f16.f32 "
                        "{%0,%1,%2,%3}, {%4,%5,%6,%7}, {%8,%9}, {%0,%1,%2,%3};"
                        : "+f"(c[mt][nt][0]), "+f"(c[mt][nt][1]),
                          "+f"(c[mt][nt][2]), "+f"(c[mt][nt][3])
                        : "r"(a[mt][0]), "r"(a[mt][1]), "r"(a[mt][2]), "r"(a[mt][3]),
                          "r"(b[nt][0]), "r"(b[nt][1]));
        }

        // store next A tile (buffer (kt+1)&1 was last read at kt-1, pre-sync)
        if (kt + 1 < NKT) {
            unsigned* A = As[(kt+1) & 1];
            A[ar*8      + ((wa+0) ^ sw)] = packh2(a0v.x, a0v.y);
            A[ar*8      + ((wa+1) ^ sw)] = packh2(a0v.z, a0v.w);
            A[(ar+64)*8 + ((wa+0) ^ sw)] = packh2(a1v.x, a1v.y);
            A[(ar+64)*8 + ((wa+1) ^ sw)] = packh2(a1v.z, a1v.w);
        }
        __syncthreads();
    }

    // Epilogue -> fp16
    #pragma unroll
    for (int mt = 0; mt < 2; ++mt) {
        int r0 = m0 + rB + mt * 16 + (lane >> 2);
        #pragma unroll
        for (int nt = 0; nt < 4; ++nt) {
            int cc = n0 + nB + nt * 8 + (lane & 3) * 2;
            if (r0 < ROWS) {
                __half2 h = __floats2half2_rn(c[mt][nt][0], c[mt][nt][1]);
                *(__half2*)&Y[(size_t)r0 * DD + cc] = h;
            }
            if (r0 + 8 < ROWS) {
                __half2 h = __floats2half2_rn(c[mt][nt][2], c[mt][nt][3]);
                *(__half2*)&Y[(size_t)(r0 + 8) * DD + cc] = h;
            }
        }
    }
}

// ---------------------------------------------------------------------------
// Edge kernel: 4 edges per warp, batch = blockIdx.y. All 8 mask loads then
// all 8 row-gather LDG.128s issued before compute -> MLP ~8. Per-head dot
// in half2 HFMA2 (4 fma per 8 dims), fold to f32, 2 xor shfls; quad leaders
// exp/store/atomic. Global-max shift algebraically redundant in e/(seg+eps).
// ---------------------------------------------------------------------------
__global__ __launch_bounds__(256) void edge_kernel(const void* __restrict__ mask,
                                                   float* __restrict__ out)
{
    const int is64 = g_is64;
    const int b    = blockIdx.y;
    const int e0   = (int)((blockIdx.x * 8u + (threadIdx.x >> 5)) * 4u);
    const int lane = threadIdx.x & 31;

    int iv[4], jv[4];
    #pragma unroll
    for (int u = 0; u < 4; ++u) {
        iv[u] = mask_at(mask, 0, e0 + u, is64);
        jv[u] = mask_at(mask, 1, e0 + u, is64);
    }

    uint4 qv[4], kv[4];
    #pragma unroll
    for (int u = 0; u < 4; ++u) {
        qv[u] = ((const uint4*)(g_qh + (unsigned)(b * NN + iv[u]) * DD))[lane];
        kv[u] = ((const uint4*)(g_kh + (unsigned)(b * NN + jv[u]) * DD))[lane];
    }

    float s[4];
    #pragma unroll
    for (int u = 0; u < 4; ++u) {
        const __half2* qp = (const __half2*)&qv[u];
        const __half2* kp = (const __half2*)&kv[u];
        __half2 acc = __float2half2_rn(0.0f);
        #pragma unroll
        for (int p = 0; p < 4; ++p) acc = __hfma2(qp[p], kp[p], acc);
        float2 f = __half22float2(acc);
        float a = f.x + f.y;
        a += __shfl_xor_sync(0xffffffffu, a, 1);
        a += __shfl_xor_sync(0xffffffffu, a, 2);
        s[u] = a;                          // quad 4h..4h+3 hold head-h sum
    }

    if ((lane & 3) == 0) {
        const int h = lane >> 2;
        #pragma unroll
        for (int u = 0; u < 4; ++u) {
            float v = __expf(s[u] * 0.0625f);   // /sqrt(256)
            out[(unsigned)(b * MM + e0 + u) * HH + h] = v;
            atomicAdd(&g_seg[(unsigned)(b * NN + iv[u]) * HH + h], v);
        }
    }
}

// ---------------------------------------------------------------------------
// inv: one rcp per (b, node, h)
// ---------------------------------------------------------------------------
__global__ void inv_kernel() {
    int idx = blockIdx.x * blockDim.x + threadIdx.x;
    if (idx < BB*NN*HH) g_inv[idx] = 1.0f / (g_seg[idx] + 1e-16f);
}

// ---------------------------------------------------------------------------
// Normalize: thread per edge, batch = blockIdx.y; float4 x2 multiply.
// ---------------------------------------------------------------------------
__global__ __launch_bounds__(256) void norm_kernel(const void* __restrict__ mask,
                                                   float* __restrict__ out)
{
    const int is64 = g_is64;
    const int b = blockIdx.y;
    const int e = (int)(blockIdx.x * 256u + threadIdx.x);
    const int i = mask_at(mask, 0, e, is64);

    const float4* iv = (const float4*)(g_inv + (unsigned)(b * NN + i) * HH);
    float4 s0 = iv[0], s1 = iv[1];
    float4* op = (float4*)(out + (unsigned)(b * MM + e) * HH);
    float4 o0 = op[0], o1 = op[1];
    o0.x *= s0.x; o0.y *= s0.y; o0.z *= s0.z; o0.w *= s0.w;
    o1.x *= s1.x; o1.y *= s1.y; o1.z *= s1.z; o1.w *= s1.w;
    op[0] = o0; op[1] = o1;
}

// ---------------------------------------------------------------------------
extern "C" void kernel_launch(void* const* d_in, const int* in_sizes, int n_in,
                              void* d_out, int out_size)
{
    const float* x_q  = (const float*)d_in[0];
    const float* x_k  = (const float*)d_in[1];
    const void*  mask = d_in[2];
    const float* w_q  = (const float*)d_in[3];
    const float* w_k  = (const float*)d_in[4];
    float* out = (float*)d_out;

    detect_kernel<<<1, 32>>>((const unsigned*)mask);
    zero_seg_kernel<<<(BB*NN*HH + 255) / 256, 256>>>();

    dim3 gg((ROWS + BM - 1) / BM, DD / BNJ, 2);   // (157, 4, 2)
    gemm_kernel<<<gg, 256>>>(x_q, x_k, w_q, w_k);

    dim3 ge(MM / 32, BB);           // 8 warps/block x 4 edges/warp, exact cover
    edge_kernel<<<ge, 256>>>(mask, out);

    inv_kernel<<<(BB*NN*HH + 255) / 256, 256>>>();

    dim3 gn(MM / 256, BB);          // exact cover
    norm_kernel<<<gn, 256>>>(mask, out);
}

// round 13
// speedup vs baseline: 1.0030x; 1.0030x over previous
#include <cuda_runtime.h>
#include <cuda_fp16.h>
#include <cstdint>
#include <cstddef>

#define BB 2
#define NN 10000
#define MM 320000
#define DD 256
#define HH 8

#define ROWS (BB*NN)   // 20000 rows per projection
#define BM 128
#define BN 128
#define BK 16
#define NKT (DD/BK)    // 16 k-tiles

// Scratch (allocation-free rule: device globals)
__device__ __half g_qh[(size_t)BB*NN*DD];
__device__ __half g_kh[(size_t)BB*NN*DD];
__device__ float g_seg[(size_t)BB*NN*HH];
__device__ float g_inv[(size_t)BB*NN*HH];
__device__ int   g_is64;

// ---------------------------------------------------------------------------
// mask dtype detection: values in [0, N) so int64 high words are all zero.
// ---------------------------------------------------------------------------
__global__ void detect_kernel(const unsigned* __restrict__ w) {
    if (threadIdx.x == 0) {
        int is64 = 1;
        #pragma unroll 1
        for (int t = 0; t < 64; ++t) {
            if (w[2*t + 1] != 0u) { is64 = 0; break; }
        }
        g_is64 = is64;
    }
}

__device__ __forceinline__ int mask_at(const void* m, int row, int e, int is64) {
    if (is64) return (int)((const long long*)m)[(unsigned)(row*MM + e)];
    return ((const int*)m)[(unsigned)(row*MM + e)];
}

__global__ void zero_seg_kernel() {
    int i = blockIdx.x * blockDim.x + threadIdx.x;
    if (i < BB*NN*HH) g_seg[i] = 0.0f;
}

// ---------------------------------------------------------------------------
// FP16 tensor-core GEMM (m16n8k16, f32 accum), BM=BN=128, 16 mma/barrier.
// A smem: word = row*8 + (w ^ (row&7))   (proven conflict-free)
// B smem: word = p*128 + (n ^ 8p), p = k-pair 0..7. Producer: 2 coalesced
//   LDG.128 + 1 STS.128/thread (swizzle preserves low-2 bits -> contiguous).
//   Consumer banks ((8*nt+g) ^ 8t) mod 32: permutation over (g,t).
// Double-buffered, 1-tile register prefetch for both A and B.
// Y[20000,256](fp16) = X[20000,256] @ W[256,256];  z=0: q, z=1: k
// ---------------------------------------------------------------------------
__device__ __forceinline__ unsigned packh2(float a, float b) {
    __half2 h = __floats2half2_rn(a, b);   // lo=a, hi=b  (k, k+1)
    return *(unsigned*)&h;
}

__global__ __launch_bounds__(256, 2) void gemm_kernel(
    const float* __restrict__ x_q, const float* __restrict__ x_k,
    const float* __restrict__ w_q, const float* __restrict__ w_k)
{
    __shared__ unsigned As[2][BM * 8];   // 8 KB
    __shared__ unsigned Bs[2][BN * 8];   // 8 KB  (8 k-pairs x 128 n)

    const float* X = blockIdx.z ? x_k : x_q;
    const float* W = blockIdx.z ? w_k : w_q;
    __half*      Y = blockIdx.z ? g_kh : g_qh;

    const int m0   = blockIdx.x * BM;
    const int n0   = blockIdx.y * BN;
    const int tid  = threadIdx.x;
    const int lane = tid & 31;
    const int warp = tid >> 5;
    const int rB   = (warp & 3) * 32;   // warp row base
    const int nB   = (warp >> 2) * 64;  // warp col base

    // ---- A producer indices ----
    const int ar = tid >> 2;            // rows ar, ar+64
    const int wa = (tid & 3) * 2;       // word base
    const int ac = (tid & 3) * 4;       // float col base
    const int sw = ar & 7;              // == (ar+64)&7

    int gr0 = m0 + ar;      if (gr0 >= ROWS) gr0 = ROWS - 1;
    int gr1 = m0 + ar + 64; if (gr1 >= ROWS) gr1 = ROWS - 1;
    const float* xp0 = X + (size_t)gr0 * DD + ac;
    const float* xp1 = X + (size_t)gr1 * DD + ac;

    // ---- B producer indices: p = k-pair, f4 = n/4 group ----
    const int bp  = tid >> 5;           // 0..7
    const int bf4 = tid & 31;           // 0..31
    const int bwbase = bp * 128 + ((bf4 * 4) ^ (bp * 8));  // 4-word aligned
    const float* wp0 = W + (size_t)(2*bp)   * DD + n0 + bf4 * 4;
    const float* wp1 = W + (size_t)(2*bp+1) * DD + n0 + bf4 * 4;

    float c[2][8][4];
    #pragma unroll
    for (int mt = 0; mt < 2; ++mt)
        #pragma unroll
        for (int nt = 0; nt < 8; ++nt)
            #pragma unroll
            for (int r = 0; r < 4; ++r) c[mt][nt][r] = 0.0f;

    float4 a0v = *(const float4*)xp0;
    float4 a1v = *(const float4*)xp1;
    float4 b0v = *(const float4*)wp0;
    float4 b1v = *(const float4*)wp1;

    {   // store tile 0 into buf 0
        unsigned* A = As[0];
        A[ar*8      + ((wa+0) ^ sw)] = packh2(a0v.x, a0v.y);
        A[ar*8      + ((wa+1) ^ sw)] = packh2(a0v.z, a0v.w);
        A[(ar+64)*8 + ((wa+0) ^ sw)] = packh2(a1v.x, a1v.y);
        A[(ar+64)*8 + ((wa+1) ^ sw)] = packh2(a1v.z, a1v.w);
        uint4 pkt;
        pkt.x = packh2(b0v.x, b1v.x);
        pkt.y = packh2(b0v.y, b1v.y);
        pkt.z = packh2(b0v.z, b1v.z);
        pkt.w = packh2(b0v.w, b1v.w);
        *(uint4*)&Bs[0][bwbase] = pkt;
    }
    __syncthreads();

    #pragma unroll 2
    for (int kt = 0; kt < NKT; ++kt) {
        // prefetch next tile into registers (hidden behind compute)
        if (kt + 1 < NKT) {
            int ko = (kt + 1) * BK;
            a0v = *(const float4*)(xp0 + ko);
            a1v = *(const float4*)(xp1 + ko);
            b0v = *(const float4*)(wp0 + (size_t)ko * DD);
            b1v = *(const float4*)(wp1 + (size_t)ko * DD);
        }

        // compute: one m16n8k16 sweep covers BK=16
        {
            const unsigned* A  = As[kt & 1];
            const unsigned* Bp = Bs[kt & 1];
            const int t = lane & 3;
            const int g = lane >> 2;
            unsigned a[2][4], b[8][2];
            #pragma unroll
            for (int mt = 0; mt < 2; ++mt) {
                int r = rB + mt * 16 + g;         // r&7 == g
                a[mt][0] = A[r*8     + (t ^ g)];
                a[mt][1] = A[(r+8)*8 + (t ^ g)];
                a[mt][2] = A[r*8     + ((t+4) ^ g)];
                a[mt][3] = A[(r+8)*8 + ((t+4) ^ g)];
            }
            #pragma unroll
            for (int nt = 0; nt < 8; ++nt) {
                int col = nB + nt * 8 + g;
                b[nt][0] = Bp[t*128     + (col ^ (8*t))];
                b[nt][1] = Bp[(t+4)*128 + (col ^ (8*(t+4)))];
            }
            #pragma unroll
            for (int mt = 0; mt < 2; ++mt)
                #pragma unroll
                for (int nt = 0; nt < 8; ++nt)
                    asm volatile(
                        "mma.sync.aligned.m16n8k16.row.col.f32.f16.f16.f32 "
                        "{%0,%1,%2,%3}, {%4,%5,%6,%7}, {%8,%9}, {%0,%1,%2,%3};"
                        : "+f"(c[mt][nt][0]), "+f"(c[mt][nt][1]),
                          "+f"(c[mt][nt][2]), "+f"(c[mt][nt][3])
                        : "r"(a[mt][0]), "r"(a[mt][1]), "r"(a[mt][2]), "r"(a[mt][3]),
                          "r"(b[nt][0]), "r"(b[nt][1]));
        }

        // store next tile (other buffer's readers finished at previous sync)
        if (kt + 1 < NKT) {
            unsigned* A = As[(kt+1) & 1];
            A[ar*8      + ((wa+0) ^ sw)] = packh2(a0v.x, a0v.y);
            A[ar*8      + ((wa+1) ^ sw)] = packh2(a0v.z, a0v.w);
            A[(ar+64)*8 + ((wa+0) ^ sw)] = packh2(a1v.x, a1v.y);
            A[(ar+64)*8 + ((wa+1) ^ sw)] = packh2(a1v.z, a1v.w);
            uint4 pkt;
            pkt.x = packh2(b0v.x, b1v.x);
            pkt.y = packh2(b0v.y, b1v.y);
            pkt.z = packh2(b0v.z, b1v.z);
            pkt.w = packh2(b0v.w, b1v.w);
            *(uint4*)&Bs[(kt+1) & 1][bwbase] = pkt;
        }
        __syncthreads();
    }

    // Epilogue -> fp16
    #pragma unroll
    for (int mt = 0; mt < 2; ++mt) {
        int r0 = m0 + rB + mt * 16 + (lane >> 2);
        #pragma unroll
        for (int nt = 0; nt < 8; ++nt) {
            int cc = n0 + nB + nt * 8 + (lane & 3) * 2;
            if (r0 < ROWS) {
                __half2 h = __floats2half2_rn(c[mt][nt][0], c[mt][nt][1]);
                *(__half2*)&Y[(size_t)r0 * DD + cc] = h;
            }
            if (r0 + 8 < ROWS) {
                __half2 h = __floats2half2_rn(c[mt][nt][2], c[mt][nt][3]);
                *(__half2*)&Y[(size_t)(r0 + 8) * DD + cc] = h;
            }
        }
    }
}

// ---------------------------------------------------------------------------
// Edge kernel: 4 edges per warp. All 8 mask loads then all 8 row-gather
// LDG.128s issued before compute -> MLP ~8. HFMA2 dot, 2 xor shfls, exp on
// all lanes, 4 gather shfls; lanes 0 & 16 emit ONE STG.128 + ONE v4 RED each
// (16 LSU lane-ops/edge -> 4). Global-max shift redundant in e/(seg+eps).
// ---------------------------------------------------------------------------
__global__ __launch_bounds__(256) void edge_kernel(const void* __restrict__ mask,
                                                   float* __restrict__ out)
{
    const int is64 = g_is64;
    const int b    = blockIdx.y;
    const int e0   = (int)((blockIdx.x * 8u + (threadIdx.x >> 5)) * 4u);
    const int lane = threadIdx.x & 31;

    int iv[4], jv[4];
    #pragma unroll
    for (int u = 0; u < 4; ++u) {
        iv[u] = mask_at(mask, 0, e0 + u, is64);
        jv[u] = mask_at(mask, 1, e0 + u, is64);
    }

    uint4 qv[4], kv[4];
    #pragma unroll
    for (int u = 0; u < 4; ++u) {
        qv[u] = ((const uint4*)(g_qh + (unsigned)(b * NN + iv[u]) * DD))[lane];
        kv[u] = ((const uint4*)(g_kh + (unsigned)(b * NN + jv[u]) * DD))[lane];
    }

    const int src = (lane & 16);          // gather base: heads 0-3 / 4-7
    #pragma unroll
    for (int u = 0; u < 4; ++u) {
        const __half2* qp = (const __half2*)&qv[u];
        const __half2* kp = (const __half2*)&kv[u];
        __half2 acc = __float2half2_rn(0.0f);
        #pragma unroll
        for (int p = 0; p < 4; ++p) acc = __hfma2(qp[p], kp[p], acc);
        float2 f = __half22float2(acc);
        float a = f.x + f.y;
        a += __shfl_xor_sync(0xffffffffu, a, 1);
        a += __shfl_xor_sync(0xffffffffu, a, 2);   // whole quad holds head sum
        float v = __expf(a * 0.0625f);             // /sqrt(256)

        float4 vv;
        vv.x = __shfl_sync(0xffffffffu, v, src + 0);
        vv.y = __shfl_sync(0xffffffffu, v, src + 4);
        vv.z = __shfl_sync(0xffffffffu, v, src + 8);
        vv.w = __shfl_sync(0xffffffffu, v, src + 12);

        if ((lane & 15) == 0) {
            const unsigned ho = (unsigned)(lane >> 4) * 4u;   // 0 or 4
            *(float4*)&out[(unsigned)(b * MM + e0 + u) * HH + ho] = vv;
            float* sp = &g_seg[(unsigned)(b * NN + iv[u]) * HH + ho];
            asm volatile("red.global.add.v4.f32 [%0], {%1,%2,%3,%4};"
                         :: "l"(sp), "f"(vv.x), "f"(vv.y), "f"(vv.z), "f"(vv.w)
                         : "memory");
        }
    }
}

// ---------------------------------------------------------------------------
// inv: one rcp per (b, node, h)
// ---------------------------------------------------------------------------
__global__ void inv_kernel() {
    int idx = blockIdx.x * blockDim.x + threadIdx.x;
    if (idx < BB*NN*HH) g_inv[idx] = 1.0f / (g_seg[idx] + 1e-16f);
}

// ---------------------------------------------------------------------------
// Normalize: thread per edge, batch = blockIdx.y; float4 x2 multiply.
// ---------------------------------------------------------------------------
__global__ __launch_bounds__(256) void norm_kernel(const void* __restrict__ mask,
                                                   float* __restrict__ out)
{
    const int is64 = g_is64;
    const int b = blockIdx.y;
    const int e = (int)(blockIdx.x * 256u + threadIdx.x);
    const int i = mask_at(mask, 0, e, is64);

    const float4* iv = (const float4*)(g_inv + (unsigned)(b * NN + i) * HH);
    float4 s0 = iv[0], s1 = iv[1];
    float4* op = (float4*)(out + (unsigned)(b * MM + e) * HH);
    float4 o0 = op[0], o1 = op[1];
    o0.x *= s0.x; o0.y *= s0.y; o0.z *= s0.z; o0.w *= s0.w;
    o1.x *= s1.x; o1.y *= s1.y; o1.z *= s1.z; o1.w *= s1.w;
    op[0] = o0; op[1] = o1;
}

// ---------------------------------------------------------------------------
extern "C" void kernel_launch(void* const* d_in, const int* in_sizes, int n_in,
                              void* d_out, int out_size)
{
    const float* x_q  = (const float*)d_in[0];
    const float* x_k  = (const float*)d_in[1];
    const void*  mask = d_in[2];
    const float* w_q  = (const float*)d_in[3];
    const float* w_k  = (const float*)d_in[4];
    float* out = (float*)d_out;

    detect_kernel<<<1, 32>>>((const unsigned*)mask);
    zero_seg_kernel<<<(BB*NN*HH + 255) / 256, 256>>>();

    dim3 gg((ROWS + BM - 1) / BM, DD / BN, 2);    // (157, 2, 2)
    gemm_kernel<<<gg, 256>>>(x_q, x_k, w_q, w_k);

    dim3 ge(MM / 32, BB);           // 8 warps/block x 4 edges/warp, exact cover
    edge_kernel<<<ge, 256>>>(mask, out);

    inv_kernel<<<(BB*NN*HH + 255) / 256, 256>>>();

    dim3 gn(MM / 256, BB);          // exact cover
    norm_kernel<<<gn, 256>>>(mask, out);
}

// round 15
// speedup vs baseline: 1.1670x; 1.1635x over previous
#include <cuda_runtime.h>
#include <cuda_fp16.h>
#include <cstdint>
#include <cstddef>

#define BB 2
#define NN 10000
#define MM 320000
#define DD 256
#define HH 8

#define ROWS (BB*NN)   // 20000 rows per projection
#define BM 128
#define BN 128
#define BK 16
#define NKT (DD/BK)    // 16 k-tiles

// Scratch (allocation-free rule: device globals)
__device__ __half g_qh[(size_t)BB*NN*DD];
__device__ __half g_kh[(size_t)BB*NN*DD];
__device__ float g_seg[(size_t)BB*NN*HH];
__device__ float g_inv[(size_t)BB*NN*HH];
__device__ int   g_is64;

// ---------------------------------------------------------------------------
// init: zero seg buffer; block 0 also detects mask dtype (int64 high words of
// values < N are all zero; int32 false-positive prob over 64 words ~1e-256).
// ---------------------------------------------------------------------------
__global__ void init_kernel(const unsigned* __restrict__ w) {
    int i = blockIdx.x * blockDim.x + threadIdx.x;
    if (i < BB*NN*HH) g_seg[i] = 0.0f;
    if (blockIdx.x == 0 && threadIdx.x == 0) {
        int is64 = 1;
        #pragma unroll 1
        for (int t = 0; t < 64; ++t) {
            if (w[2*t + 1] != 0u) { is64 = 0; break; }
        }
        g_is64 = is64;
    }
}

__device__ __forceinline__ int mask_at(const void* m, int row, int e, int is64) {
    if (is64) return (int)((const long long*)m)[(unsigned)(row*MM + e)];
    return ((const int*)m)[(unsigned)(row*MM + e)];
}

// ---------------------------------------------------------------------------
// FP16 tensor-core GEMM (m16n8k16, f32 accum), BM=BN=128, 16 mma/barrier.
// A smem: word = row*8 + (w ^ (row&7))   (conflict-free, proven)
// B smem: word = p*128 + (n ^ 8p), p = k-pair. Producer: 2 coalesced LDG.128
//   + 1 STS.128/thread. Consumer banks permutation over (g,t).
// Double-buffered, 1-tile register prefetch for both A and B.  [R13, ~20us]
// ---------------------------------------------------------------------------
__device__ __forceinline__ unsigned packh2(float a, float b) {
    __half2 h = __floats2half2_rn(a, b);   // lo=a, hi=b  (k, k+1)
    return *(unsigned*)&h;
}

__global__ __launch_bounds__(256, 2) void gemm_kernel(
    const float* __restrict__ x_q, const float* __restrict__ x_k,
    const float* __restrict__ w_q, const float* __restrict__ w_k)
{
    __shared__ unsigned As[2][BM * 8];   // 8 KB
    __shared__ unsigned Bs[2][BN * 8];   // 8 KB

    const float* X = blockIdx.z ? x_k : x_q;
    const float* W = blockIdx.z ? w_k : w_q;
    __half*      Y = blockIdx.z ? g_kh : g_qh;

    const int m0   = blockIdx.x * BM;
    const int n0   = blockIdx.y * BN;
    const int tid  = threadIdx.x;
    const int lane = tid & 31;
    const int warp = tid >> 5;
    const int rB   = (warp & 3) * 32;
    const int nB   = (warp >> 2) * 64;

    const int ar = tid >> 2;
    const int wa = (tid & 3) * 2;
    const int ac = (tid & 3) * 4;
    const int sw = ar & 7;

    int gr0 = m0 + ar;      if (gr0 >= ROWS) gr0 = ROWS - 1;
    int gr1 = m0 + ar + 64; if (gr1 >= ROWS) gr1 = ROWS - 1;
    const float* xp0 = X + (size_t)gr0 * DD + ac;
    const float* xp1 = X + (size_t)gr1 * DD + ac;

    const int bp  = tid >> 5;
    const int bf4 = tid & 31;
    const int bwbase = bp * 128 + ((bf4 * 4) ^ (bp * 8));
    const float* wp0 = W + (size_t)(2*bp)   * DD + n0 + bf4 * 4;
    const float* wp1 = W + (size_t)(2*bp+1) * DD + n0 + bf4 * 4;

    float c[2][8][4];
    #pragma unroll
    for (int mt = 0; mt < 2; ++mt)
        #pragma unroll
        for (int nt = 0; nt < 8; ++nt)
            #pragma unroll
            for (int r = 0; r < 4; ++r) c[mt][nt][r] = 0.0f;

    float4 a0v = *(const float4*)xp0;
    float4 a1v = *(const float4*)xp1;
    float4 b0v = *(const float4*)wp0;
    float4 b1v = *(const float4*)wp1;

    {
        unsigned* A = As[0];
        A[ar*8      + ((wa+0) ^ sw)] = packh2(a0v.x, a0v.y);
        A[ar*8      + ((wa+1) ^ sw)] = packh2(a0v.z, a0v.w);
        A[(ar+64)*8 + ((wa+0) ^ sw)] = packh2(a1v.x, a1v.y);
        A[(ar+64)*8 + ((wa+1) ^ sw)] = packh2(a1v.z, a1v.w);
        uint4 pkt;
        pkt.x = packh2(b0v.x, b1v.x);
        pkt.y = packh2(b0v.y, b1v.y);
        pkt.z = packh2(b0v.z, b1v.z);
        pkt.w = packh2(b0v.w, b1v.w);
        *(uint4*)&Bs[0][bwbase] = pkt;
    }
    __syncthreads();

    #pragma unroll 2
    for (int kt = 0; kt < NKT; ++kt) {
        if (kt + 1 < NKT) {
            int ko = (kt + 1) * BK;
            a0v = *(const float4*)(xp0 + ko);
            a1v = *(const float4*)(xp1 + ko);
            b0v = *(const float4*)(wp0 + (size_t)ko * DD);
            b1v = *(const float4*)(wp1 + (size_t)ko * DD);
        }

        {
            const unsigned* A  = As[kt & 1];
            const unsigned* Bp = Bs[kt & 1];
            const int t = lane & 3;
            const int g = lane >> 2;
            unsigned a[2][4], b[8][2];
            #pragma unroll
            for (int mt = 0; mt < 2; ++mt) {
                int r = rB + mt * 16 + g;
                a[mt][0] = A[r*8     + (t ^ g)];
                a[mt][1] = A[(r+8)*8 + (t ^ g)];
                a[mt][2] = A[r*8     + ((t+4) ^ g)];
                a[mt][3] = A[(r+8)*8 + ((t+4) ^ g)];
            }
            #pragma unroll
            for (int nt = 0; nt < 8; ++nt) {
                int col = nB + nt * 8 + g;
                b[nt][0] = Bp[t*128     + (col ^ (8*t))];
                b[nt][1] = Bp[(t+4)*128 + (col ^ (8*(t+4)))];
            }
            #pragma unroll
            for (int mt = 0; mt < 2; ++mt)
                #pragma unroll
                for (int nt = 0; nt < 8; ++nt)
                    asm volatile(
                        "mma.sync.aligned.m16n8k16.row.col.f32.f16.f16.f32 "
                        "{%0,%1,%2,%3}, {%4,%5,%6,%7}, {%8,%9}, {%0,%1,%2,%3};"
                        : "+f"(c[mt][nt][0]), "+f"(c[mt][nt][1]),
                          "+f"(c[mt][nt][2]), "+f"(c[mt][nt][3])
                        : "r"(a[mt][0]), "r"(a[mt][1]), "r"(a[mt][2]), "r"(a[mt][3]),
                          "r"(b[nt][0]), "r"(b[nt][1]));
        }

        if (kt + 1 < NKT) {
            unsigned* A = As[(kt+1) & 1];
            A[ar*8      + ((wa+0) ^ sw)] = packh2(a0v.x, a0v.y);
            A[ar*8      + ((wa+1) ^ sw)] = packh2(a0v.z, a0v.w);
            A[(ar+64)*8 + ((wa+0) ^ sw)] = packh2(a1v.x, a1v.y);
            A[(ar+64)*8 + ((wa+1) ^ sw)] = packh2(a1v.z, a1v.w);
            uint4 pkt;
            pkt.x = packh2(b0v.x, b1v.x);
            pkt.y = packh2(b0v.y, b1v.y);
            pkt.z = packh2(b0v.z, b1v.z);
            pkt.w = packh2(b0v.w, b1v.w);
            *(uint4*)&Bs[(kt+1) & 1][bwbase] = pkt;
        }
        __syncthreads();
    }

    #pragma unroll
    for (int mt = 0; mt < 2; ++mt) {
        int r0 = m0 + rB + mt * 16 + (lane >> 2);
        #pragma unroll
        for (int nt = 0; nt < 8; ++nt) {
            int cc = n0 + nB + nt * 8 + (lane & 3) * 2;
            if (r0 < ROWS) {
                __half2 h = __floats2half2_rn(c[mt][nt][0], c[mt][nt][1]);
                *(__half2*)&Y[(size_t)r0 * DD + cc] = h;
            }
            if (r0 + 8 < ROWS) {
                __half2 h = __floats2half2_rn(c[mt][nt][2], c[mt][nt][3]);
                *(__half2*)&Y[(size_t)(r0 + 8) * DD + cc] = h;
            }
        }
    }
}

// ---------------------------------------------------------------------------
// Edge kernel [exact R11 form, measured 50.1us]: 4 edges per warp. All 8 mask
// loads then all 8 row-gather LDG.128s before compute -> MLP ~8. HFMA2 dot,
// 2 xor shfls; quad leaders (8 lanes) do exp + scalar store + scalar
// atomicAdd (these coalesce warp-wide). Global-max shift is algebraically
// redundant in e/(seg+eps).
// ---------------------------------------------------------------------------
__global__ __launch_bounds__(256) void edge_kernel(const void* __restrict__ mask,
                                                   float* __restrict__ out)
{
    const int is64 = g_is64;
    const int b    = blockIdx.y;
    const int e0   = (int)((blockIdx.x * 8u + (threadIdx.x >> 5)) * 4u);
    const int lane = threadIdx.x & 31;

    int iv[4], jv[4];
    #pragma unroll
    for (int u = 0; u < 4; ++u) {
        iv[u] = mask_at(mask, 0, e0 + u, is64);
        jv[u] = mask_at(mask, 1, e0 + u, is64);
    }

    uint4 qv[4], kv[4];
    #pragma unroll
    for (int u = 0; u < 4; ++u) {
        qv[u] = ((const uint4*)(g_qh + (unsigned)(b * NN + iv[u]) * DD))[lane];
        kv[u] = ((const uint4*)(g_kh + (unsigned)(b * NN + jv[u]) * DD))[lane];
    }

    float s[4];
    #pragma unroll
    for (int u = 0; u < 4; ++u) {
        const __half2* qp = (const __half2*)&qv[u];
        const __half2* kp = (const __half2*)&kv[u];
        __half2 acc = __float2half2_rn(0.0f);
        #pragma unroll
        for (int p = 0; p < 4; ++p) acc = __hfma2(qp[p], kp[p], acc);
        float2 f = __half22float2(acc);
        float a = f.x + f.y;
        a += __shfl_xor_sync(0xffffffffu, a, 1);
        a += __shfl_xor_sync(0xffffffffu, a, 2);
        s[u] = a;                          // quad 4h..4h+3 hold head-h sum
    }

    if ((lane & 3) == 0) {
        const int h = lane >> 2;
        #pragma unroll
        for (int u = 0; u < 4; ++u) {
            float v = __expf(s[u] * 0.0625f);   // /sqrt(256)
            out[(unsigned)(b * MM + e0 + u) * HH + h] = v;
            atomicAdd(&g_seg[(unsigned)(b * NN + iv[u]) * HH + h], v);
        }
    }
}

// ---------------------------------------------------------------------------
// inv: one rcp per (b, node, h)
// ---------------------------------------------------------------------------
__global__ void inv_kernel() {
    int idx = blockIdx.x * blockDim.x + threadIdx.x;
    if (idx < BB*NN*HH) g_inv[idx] = 1.0f / (g_seg[idx] + 1e-16f);
}

// ---------------------------------------------------------------------------
// Normalize: 2 edges per thread (MLP), batch = blockIdx.y; float4 multiply.
// ---------------------------------------------------------------------------
__global__ __launch_bounds__(256) void norm_kernel(const void* __restrict__ mask,
                                                   float* __restrict__ out)
{
    const int is64 = g_is64;
    const int b  = blockIdx.y;
    const int e0 = (int)((blockIdx.x * 256u + threadIdx.x) * 2u);

    const int i0 = mask_at(mask, 0, e0,     is64);
    const int i1 = mask_at(mask, 0, e0 + 1, is64);

    const float4* iva = (const float4*)(g_inv + (unsigned)(b * NN + i0) * HH);
    const float4* ivb = (const float4*)(g_inv + (unsigned)(b * NN + i1) * HH);
    float4* opa = (float4*)(out + (unsigned)(b * MM + e0) * HH);

    float4 s0 = iva[0], s1 = iva[1];
    float4 s2 = ivb[0], s3 = ivb[1];
    float4 o0 = opa[0], o1 = opa[1], o2 = opa[2], o3 = opa[3];

    o0.x *= s0.x; o0.y *= s0.y; o0.z *= s0.z; o0.w *= s0.w;
    o1.x *= s1.x; o1.y *= s1.y; o1.z *= s1.z; o1.w *= s1.w;
    o2.x *= s2.x; o2.y *= s2.y; o2.z *= s2.z; o2.w *= s2.w;
    o3.x *= s3.x; o3.y *= s3.y; o3.z *= s3.z; o3.w *= s3.w;

    opa[0] = o0; opa[1] = o1; opa[2] = o2; opa[3] = o3;
}

// ---------------------------------------------------------------------------
extern "C" void kernel_launch(void* const* d_in, const int* in_sizes, int n_in,
                              void* d_out, int out_size)
{
    const float* x_q  = (const float*)d_in[0];
    const float* x_k  = (const float*)d_in[1];
    const void*  mask = d_in[2];
    const float* w_q  = (const float*)d_in[3];
    const float* w_k  = (const float*)d_in[4];
    float* out = (float*)d_out;

    init_kernel<<<(BB*NN*HH + 255) / 256, 256>>>((const unsigned*)mask);

    dim3 gg((ROWS + BM - 1) / BM, DD / BN, 2);    // (157, 2, 2)
    gemm_kernel<<<gg, 256>>>(x_q, x_k, w_q, w_k);

    dim3 ge(MM / 32, BB);           // 8 warps/block x 4 edges/warp, exact cover
    edge_kernel<<<ge, 256>>>(mask, out);

    inv_kernel<<<(BB*NN*HH + 255) / 256, 256>>>();

    dim3 gn(MM / 512, BB);          // 2 edges/thread, exact cover
    norm_kernel<<<gn, 256>>>(mask, out);
}